// round 7
// baseline (speedup 1.0000x reference)
#include <cuda_runtime.h>
#include <math.h>

#define N 320
#define D 128
#define NMAT 3
#define RHO_C 10.0f
#define MARGIN_C 0.2f
#define TAU_C 1.3f
#define SEMIHARD_THRESH_C 0.01f
#define EPS_C 1e-12f
#define NTRI  210                // 20*21/2 lower-triangle tiles

// ---------------- device scratch (no allocations allowed) ----------------
__device__ float4 g_tk4[N][N];       // (d_emb[i][k], bk=1-pw, RHO*bk, pw)
__device__ float  g_partden[NTRI];   // per-tile pw sums (x2 for off-diag)
__device__ float  g_partnum[N];      // per-i partial sums of pos*pair_w
__device__ unsigned int g_counter;   // last-block ticket for fused final

// ---------------- kernel 1: fused norms + distances + pair weights ----------
// 210 lower-triangle 16x16 tiles, 256 threads. Mirrors results to (j,i).
#define PADW 132
__global__ void __launch_bounds__(256) k_distpw(const float* __restrict__ src,
                                                const float* __restrict__ emb) {
    // decode lower-triangle tile (bi >= bj)
    int b = blockIdx.x;
    int bi = (int)((sqrtf(8.0f * (float)b + 1.0f) - 1.0f) * 0.5f);
    while ((bi + 1) * (bi + 2) / 2 <= b) bi++;
    while (bi * (bi + 1) / 2 > b) bi--;
    int bj = b - bi * (bi + 1) / 2;
    int i0 = bi * 16, j0 = bj * 16;

    __shared__ float Ai[16][PADW];
    __shared__ float Aj[16][PADW];
    __shared__ float s_sq[32];   // [0..15]=i rows, [16..31]=j rows
    __shared__ float s_ri[32];

    int t  = threadIdx.x;
    int tx = t & 15, ty = t >> 4;
    int lane = t & 31, warp = t >> 5;
    int i = i0 + ty, j = j0 + tx;

    if (b == 0 && t == 0) g_counter = 0;   // reset ticket (precedes k_triplet)

    float dsum = 0.0f, demb = 0.0f;

    #pragma unroll 1
    for (int m = 0; m < NMAT; m++) {
        __syncthreads();  // protect previous iteration's smem reads
        const float* base = (m < 2) ? (src + (size_t)m * N * D) : emb;
        for (int e = t; e < 16 * 32; e += 256) {
            int r = e >> 5, c4 = e & 31;
            *(float4*)&Ai[r][c4 * 4] = ((const float4*)(base + (size_t)(i0 + r) * D))[c4];
            *(float4*)&Aj[r][c4 * 4] = ((const float4*)(base + (size_t)(j0 + r) * D))[c4];
        }
        __syncthreads();

        // warp-cooperative row norms: warp w handles rows 4w..4w+3 of 32
        #pragma unroll
        for (int rr = 0; rr < 4; rr++) {
            int row = warp * 4 + rr;
            const float* rp = (row < 16) ? &Ai[row][0] : &Aj[row - 16][0];
            float4 x = ((const float4*)rp)[lane];
            float ssum = x.x * x.x + x.y * x.y + x.z * x.z + x.w * x.w;
            #pragma unroll
            for (int o = 16; o > 0; o >>= 1) ssum += __shfl_xor_sync(0xffffffffu, ssum, o);
            if (lane == 0) {
                float rn = 1.0f / fmaxf(sqrtf(ssum), EPS_C);
                s_sq[row] = ssum * (rn * rn);
                s_ri[row] = rn;
            }
        }
        __syncthreads();

        const float4* ai = (const float4*)&Ai[ty][0];
        const float4* aj = (const float4*)&Aj[tx][0];
        float d0 = 0.f, d1 = 0.f, d2a = 0.f, d3 = 0.f;
        #pragma unroll 8
        for (int c = 0; c < 32; c++) {
            float4 a = ai[c];
            float4 bb = aj[c];
            d0  += a.x * bb.x;
            d1  += a.y * bb.y;
            d2a += a.z * bb.z;
            d3  += a.w * bb.w;
        }
        float dot = (d0 + d1) + (d2a + d3);
        float rij = s_ri[ty] * s_ri[16 + tx];
        float dd  = s_sq[ty] + s_sq[16 + tx] - 2.0f * (dot * rij);
        float d   = sqrtf(fmaxf(dd, 0.0f) + EPS_C);
        if (m < 2) dsum += d; else demb = d;
    }

    float davg = 0.5f * dsum;
    float pw = 1.0f / (1.0f + expf(-RHO_C * (TAU_C - davg)));
    float bk = 1.0f - pw;
    float4 rec = make_float4(demb, bk, RHO_C * bk, pw);
    g_tk4[i][j] = rec;
    if (bi != bj) g_tk4[j][i] = rec;   // bitwise symmetric by construction

    // deterministic block reduction of tile pw -> den partial (x2 off-diag)
    float v = pw;
    #pragma unroll
    for (int o = 16; o > 0; o >>= 1) v += __shfl_down_sync(0xffffffffu, v, o);
    __shared__ float swp[8];
    if (lane == 0) swp[warp] = v;
    __syncthreads();
    if (warp == 0) {
        float w = (lane < 8) ? swp[lane] : 0.0f;
        #pragma unroll
        for (int o = 4; o > 0; o >>= 1) w += __shfl_down_sync(0xffffffffu, w, o);
        if (lane == 0) g_partden[b] = (bi != bj) ? 2.0f * w : w;
    }
}

// ---------------- kernel 2: O(N^3) triplet pass + fused final ----------------
// grid: N blocks (one per i), N threads (one per j) -> 10 warps/block for
// latency hiding (round-6 160-thread version stalled at issue=55%, occ=16%).
__global__ void __launch_bounds__(N) k_triplet(float* __restrict__ out) {
    int i = blockIdx.x;
    int t = threadIdx.x;          // j

    __shared__ float4 s4[N];      // (dk, bk, rbk, pw)
    s4[t] = g_tk4[i][t];
    __syncthreads();

    float4 r = s4[t];
    float ndij = -r.x;
    float pwij = r.w;
    float npw  = -pwij;

    float maxs = 0.0f;            // max of m*bk over semihard (pwij factored out)
    float minn = 1e30f;           // min over HARD entries of m - rbk*pw

    #pragma unroll 8
    for (int k = 0; k < N; k++) {
        float4 v = s4[k];         // LDS.128 uniform broadcast
        float dk = v.x, bk = v.y, rbk = v.z;
        // diff = d[i,k] - d[i,j] (bitwise: dk + (-dij)); m = MARGIN - diff.
        // k==j -> diff==0 exactly -> m==0.2f exactly -> semihard. Do not refactor.
        float diff = dk + ndij;
        float m = MARGIN_C - diff;
        float vs = m * bk;        // m<=0 -> vs<=0, harmless vs maxs>=0
        if (m <= MARGIN_C) maxs = fmaxf(maxs, vs);
        else               minn = fminf(minn, fmaf(rbk, npw, m));
    }

    float psh = pwij * maxs;                          // pos_semihard
    float ph  = (minn < 0.0f) ? (minn + RHO_C) : 0.0f;
    float pos = psh + ((psh <= SEMIHARD_THRESH_C) ? ph : 0.0f);
    float contrib = pos * pwij;

    // deterministic block reduction (10 warps)
    float v = contrib;
    #pragma unroll
    for (int o = 16; o > 0; o >>= 1) v += __shfl_down_sync(0xffffffffu, v, o);
    __shared__ float swp[10];
    int lane = t & 31, warp = t >> 5;
    if (lane == 0) swp[warp] = v;
    __syncthreads();
    if (warp == 0 && lane == 0) {
        float w = 0.0f;
        #pragma unroll
        for (int q = 0; q < 10; q++) w += swp[q];
        g_partnum[i] = w;
    }

    // ---- fused final: last block sums everything ----
    __threadfence();
    __shared__ bool is_last;
    if (t == 0) {
        unsigned tk = atomicAdd(&g_counter, 1u);
        is_last = (tk == (unsigned)(gridDim.x - 1));
    }
    __syncthreads();
    if (!is_last) return;

    float num = 0.0f, den = 0.0f;
    for (int b2 = t; b2 < N;    b2 += N) num += __ldcg(&g_partnum[b2]);
    for (int b2 = t; b2 < NTRI; b2 += N) den += __ldcg(&g_partden[b2]);
    #pragma unroll
    for (int o = 16; o > 0; o >>= 1) {
        num += __shfl_down_sync(0xffffffffu, num, o);
        den += __shfl_down_sync(0xffffffffu, den, o);
    }
    __shared__ float sn[10], sd2[10];
    if (lane == 0) { sn[warp] = num; sd2[warp] = den; }
    __syncthreads();
    if (t == 0) {
        float fn = 0.0f, fd = 0.0f;
        #pragma unroll
        for (int q = 0; q < 10; q++) { fn += sn[q]; fd += sd2[q]; }
        out[0] = (fd > 0.0f) ? (fn / fmaxf(fd, EPS_C)) : 0.0f;
    }
}

extern "C" void kernel_launch(void* const* d_in, const int* in_sizes, int n_in,
                              void* d_out, int out_size) {
    (void)n_in; (void)out_size;
    const float* src = (const float*)d_in[0];
    const float* emb = (const float*)d_in[1];
    if (n_in >= 2 && in_sizes[0] == N * D && in_sizes[1] == 2 * N * D) {
        const float* tmp = src; src = emb; emb = tmp;
    }
    float* out = (float*)d_out;

    k_distpw<<<NTRI, 256>>>(src, emb);
    k_triplet<<<N, N>>>(out);
}

// round 8
// speedup vs baseline: 1.0491x; 1.0491x over previous
#include <cuda_runtime.h>
#include <math.h>

#define N 320
#define D 128
#define NMAT 3
#define RHO_C 10.0f
#define MARGIN_C 0.2f
#define TAU_C 1.3f
#define SEMIHARD_THRESH_C 0.01f
#define EPS_C 1e-12f
#define NTRI  210                // 20*21/2 lower-triangle tiles
#define KCH   160                // k-chunk size (N/2)

// ---------------- device scratch (no allocations allowed) ----------------
__device__ float4 g_tk4[N][N];       // (d_emb[i][k], bk=1-pw, RHO*bk, pw)
__device__ float2 g_mm[2][N][N];     // per-chunk (maxs, minn) partials
__device__ float  g_partden[NTRI];   // per-tile pw sums (x2 for off-diag)
__device__ float  g_partnum[N];      // per-i sums of pos*pair_w
__device__ unsigned int g_cnt_i[N];  // per-i chunk tickets
__device__ unsigned int g_counter;   // global ticket for fused final

// ---------------- kernel 1: fused norms + distances + pair weights ----------
#define PADW 132
__global__ void __launch_bounds__(256) k_distpw(const float* __restrict__ src,
                                                const float* __restrict__ emb) {
    int b = blockIdx.x;
    int bi = (int)((sqrtf(8.0f * (float)b + 1.0f) - 1.0f) * 0.5f);
    while ((bi + 1) * (bi + 2) / 2 <= b) bi++;
    while (bi * (bi + 1) / 2 > b) bi--;
    int bj = b - bi * (bi + 1) / 2;
    int i0 = bi * 16, j0 = bj * 16;

    __shared__ float Ai[16][PADW];
    __shared__ float Aj[16][PADW];
    __shared__ float s_sq[32];
    __shared__ float s_ri[32];

    int t  = threadIdx.x;
    int tx = t & 15, ty = t >> 4;
    int lane = t & 31, warp = t >> 5;
    int i = i0 + ty, j = j0 + tx;

    if (b == 0) {                       // reset tickets (precedes k_tripart)
        if (t == 0) g_counter = 0;
        for (int e = t; e < N; e += 256) g_cnt_i[e] = 0;
    }

    float dsum = 0.0f, demb = 0.0f;

    #pragma unroll 1
    for (int m = 0; m < NMAT; m++) {
        __syncthreads();
        const float* base = (m < 2) ? (src + (size_t)m * N * D) : emb;
        for (int e = t; e < 16 * 32; e += 256) {
            int r = e >> 5, c4 = e & 31;
            *(float4*)&Ai[r][c4 * 4] = ((const float4*)(base + (size_t)(i0 + r) * D))[c4];
            *(float4*)&Aj[r][c4 * 4] = ((const float4*)(base + (size_t)(j0 + r) * D))[c4];
        }
        __syncthreads();

        #pragma unroll
        for (int rr = 0; rr < 4; rr++) {
            int row = warp * 4 + rr;
            const float* rp = (row < 16) ? &Ai[row][0] : &Aj[row - 16][0];
            float4 x = ((const float4*)rp)[lane];
            float ssum = x.x * x.x + x.y * x.y + x.z * x.z + x.w * x.w;
            #pragma unroll
            for (int o = 16; o > 0; o >>= 1) ssum += __shfl_xor_sync(0xffffffffu, ssum, o);
            if (lane == 0) {
                float rn = 1.0f / fmaxf(sqrtf(ssum), EPS_C);
                s_sq[row] = ssum * (rn * rn);
                s_ri[row] = rn;
            }
        }
        __syncthreads();

        const float4* ai = (const float4*)&Ai[ty][0];
        const float4* aj = (const float4*)&Aj[tx][0];
        float d0 = 0.f, d1 = 0.f, d2a = 0.f, d3 = 0.f;
        #pragma unroll 8
        for (int c = 0; c < 32; c++) {
            float4 a = ai[c];
            float4 bb = aj[c];
            d0  += a.x * bb.x;
            d1  += a.y * bb.y;
            d2a += a.z * bb.z;
            d3  += a.w * bb.w;
        }
        float dot = (d0 + d1) + (d2a + d3);
        float rij = s_ri[ty] * s_ri[16 + tx];
        float dd  = s_sq[ty] + s_sq[16 + tx] - 2.0f * (dot * rij);
        float d   = sqrtf(fmaxf(dd, 0.0f) + EPS_C);
        if (m < 2) dsum += d; else demb = d;
    }

    float davg = 0.5f * dsum;
    float pw = 1.0f / (1.0f + expf(-RHO_C * (TAU_C - davg)));
    float bk = 1.0f - pw;
    float4 rec = make_float4(demb, bk, RHO_C * bk, pw);
    g_tk4[i][j] = rec;
    if (bi != bj) g_tk4[j][i] = rec;   // bitwise symmetric by construction

    float v = pw;
    #pragma unroll
    for (int o = 16; o > 0; o >>= 1) v += __shfl_down_sync(0xffffffffu, v, o);
    __shared__ float swp[8];
    if (lane == 0) swp[warp] = v;
    __syncthreads();
    if (warp == 0) {
        float w = (lane < 8) ? swp[lane] : 0.0f;
        #pragma unroll
        for (int o = 4; o > 0; o >>= 1) w += __shfl_down_sync(0xffffffffu, w, o);
        if (lane == 0) g_partden[b] = (bi != bj) ? 2.0f * w : w;
    }
}

// ---------------- kernel 2: split-k triplet pass + fused combine + final ----
// grid: 640 blocks (i = bx>>1, kc = bx&1), 320 threads (one per j).
// Each block scans k in [kc*160, kc*160+160); fmax/fmin combine across chunks
// is bit-exact (associative + commutative), so results match the single pass.
__global__ void __launch_bounds__(N) k_tripart(float* __restrict__ out) {
    int i  = blockIdx.x >> 1;
    int kc = blockIdx.x & 1;
    int t  = threadIdx.x;          // j

    __shared__ float4 s4[KCH];     // this chunk's (dk, bk, rbk, pw)
    if (t < KCH) s4[t] = g_tk4[i][kc * KCH + t];
    float4 rj = g_tk4[i][t];       // own row record (dij, .., .., pwij)
    __syncthreads();

    float ndij = -rj.x;
    float pwij = rj.w;
    float npw  = -pwij;

    float maxs = 0.0f;
    float minn = 1e30f;

    #pragma unroll 8
    for (int k = 0; k < KCH; k++) {
        float4 v = s4[k];          // LDS.128 uniform broadcast
        float dk = v.x, bk = v.y, rbk = v.z;
        // diff = d[i,k] - d[i,j] bitwise; m = MARGIN - diff.
        // k==j -> diff==0 exactly -> m==0.2f exactly -> semihard.
        float diff = dk + ndij;
        float m = MARGIN_C - diff;
        float vs = m * bk;         // m<=0 -> vs<=0, harmless vs maxs>=0
        if (m <= MARGIN_C) maxs = fmaxf(maxs, vs);
        else               minn = fminf(minn, fmaf(rbk, npw, m));
    }

    __stcg(&g_mm[kc][i][t], make_float2(maxs, minn));
    __threadfence();

    // per-i ticket: second chunk block to finish combines row i
    __shared__ bool win_i;
    if (t == 0) win_i = (atomicAdd(&g_cnt_i[i], 1u) == 1u);
    __syncthreads();
    if (win_i) {
        float2 a = __ldcg(&g_mm[0][i][t]);
        float2 b = __ldcg(&g_mm[1][i][t]);
        float mx = fmaxf(a.x, b.x);
        float mn = fminf(a.y, b.y);
        float psh = pwij * mx;                          // pos_semihard
        float ph  = (mn < 0.0f) ? (mn + RHO_C) : 0.0f;
        float pos = psh + ((psh <= SEMIHARD_THRESH_C) ? ph : 0.0f);
        float contrib = pos * pwij;

        float v = contrib;
        #pragma unroll
        for (int o = 16; o > 0; o >>= 1) v += __shfl_down_sync(0xffffffffu, v, o);
        __shared__ float swp[10];
        int lane = t & 31, warp = t >> 5;
        if (lane == 0) swp[warp] = v;
        __syncthreads();
        if (warp == 0 && lane == 0) {
            float w = 0.0f;
            #pragma unroll
            for (int q = 0; q < 10; q++) w += swp[q];
            g_partnum[i] = w;
        }

        // ---- fused final: last winning block sums everything ----
        __threadfence();
        __shared__ bool is_last;
        if (t == 0) is_last = (atomicAdd(&g_counter, 1u) == (unsigned)(N - 1));
        __syncthreads();
        if (!is_last) return;

        float num = 0.0f, den = 0.0f;
        if (t < N)    num = __ldcg(&g_partnum[t]);
        if (t < NTRI) den = __ldcg(&g_partden[t]);
        #pragma unroll
        for (int o = 16; o > 0; o >>= 1) {
            num += __shfl_down_sync(0xffffffffu, num, o);
            den += __shfl_down_sync(0xffffffffu, den, o);
        }
        __shared__ float sn[10], sd2[10];
        if (lane == 0) { sn[warp] = num; sd2[warp] = den; }
        __syncthreads();
        if (t == 0) {
            float fn = 0.0f, fd = 0.0f;
            #pragma unroll
            for (int q = 0; q < 10; q++) { fn += sn[q]; fd += sd2[q]; }
            out[0] = (fd > 0.0f) ? (fn / fmaxf(fd, EPS_C)) : 0.0f;
        }
    }
}

extern "C" void kernel_launch(void* const* d_in, const int* in_sizes, int n_in,
                              void* d_out, int out_size) {
    (void)n_in; (void)out_size;
    const float* src = (const float*)d_in[0];
    const float* emb = (const float*)d_in[1];
    if (n_in >= 2 && in_sizes[0] == N * D && in_sizes[1] == 2 * N * D) {
        const float* tmp = src; src = emb; emb = tmp;
    }
    float* out = (float*)d_out;

    k_distpw<<<NTRI, 256>>>(src, emb);
    k_tripart<<<2 * N, N>>>(out);
}

// round 9
// speedup vs baseline: 1.2332x; 1.1755x over previous
#include <cuda_runtime.h>
#include <math.h>

#define N 320
#define D 128
#define NMAT 3
#define RHO_C 10.0f
#define MARGIN_C 0.2f
#define TAU_C 1.3f
#define SEMIHARD_THRESH_C 0.01f
#define EPS_C 1e-12f
#define NTRI  210                // 20*21/2 lower-triangle tiles
#define KCH   160                // k-chunk size (N/2)

typedef unsigned long long ull;

// ---------------- device scratch (no allocations allowed) ----------------
__device__ float  g_d[NMAT][N][N];   // pairwise distances per matrix
__device__ float2 g_mm[2][N][N];     // per-chunk (maxs, minn) partials
__device__ float  g_pden[N];         // per-i row sums of pw
__device__ float  g_pnum[N];         // per-i sums of pos*pair_w
__device__ unsigned int g_cnt_i[N];  // per-i chunk tickets
__device__ unsigned int g_counter;   // global ticket for fused final

// ---------------- packed f32x2 helpers (per-lane bit-identical to scalar) ---
__device__ __forceinline__ ull add2(ull a, ull b) {
    ull r; asm("add.rn.f32x2 %0, %1, %2;" : "=l"(r) : "l"(a), "l"(b)); return r;
}
__device__ __forceinline__ ull mul2(ull a, ull b) {
    ull r; asm("mul.rn.f32x2 %0, %1, %2;" : "=l"(r) : "l"(a), "l"(b)); return r;
}
__device__ __forceinline__ ull fma2(ull a, ull b, ull c) {
    ull r; asm("fma.rn.f32x2 %0, %1, %2, %3;" : "=l"(r) : "l"(a), "l"(b), "l"(c)); return r;
}
__device__ __forceinline__ ull pack2(float lo, float hi) {
    ull r; asm("mov.b64 %0, {%1, %2};" : "=l"(r) : "f"(lo), "f"(hi)); return r;
}
__device__ __forceinline__ void unpack2(ull p, float& lo, float& hi) {
    asm("mov.b64 {%0, %1}, %2;" : "=f"(lo), "=f"(hi) : "l"(p));
}

// ---------------- kernel 1: distances only; 630 blocks = 210 tiles x 3 mats -
#define PADW 132
__global__ void __launch_bounds__(256) k_dist(const float* __restrict__ src,
                                              const float* __restrict__ emb) {
    int b  = blockIdx.x;
    int m  = b / NTRI;
    int bt = b - m * NTRI;
    int bi = (int)((sqrtf(8.0f * (float)bt + 1.0f) - 1.0f) * 0.5f);
    while ((bi + 1) * (bi + 2) / 2 <= bt) bi++;
    while (bi * (bi + 1) / 2 > bt) bi--;
    int bj = bt - bi * (bi + 1) / 2;
    int i0 = bi * 16, j0 = bj * 16;

    __shared__ float Ai[16][PADW];
    __shared__ float Aj[16][PADW];
    __shared__ float s_sq[32];
    __shared__ float s_ri[32];

    int t  = threadIdx.x;
    int tx = t & 15, ty = t >> 4;
    int lane = t & 31, warp = t >> 5;
    int i = i0 + ty, j = j0 + tx;

    if (b == 0) {                       // reset tickets (precedes k_tripart)
        if (t == 0) g_counter = 0;
        for (int e = t; e < N; e += 256) g_cnt_i[e] = 0;
    }

    const float* base = (m < 2) ? (src + (size_t)m * N * D) : emb;
    for (int e = t; e < 16 * 32; e += 256) {
        int r = e >> 5, c4 = e & 31;
        *(float4*)&Ai[r][c4 * 4] = ((const float4*)(base + (size_t)(i0 + r) * D))[c4];
        *(float4*)&Aj[r][c4 * 4] = ((const float4*)(base + (size_t)(j0 + r) * D))[c4];
    }
    __syncthreads();

    #pragma unroll
    for (int rr = 0; rr < 4; rr++) {
        int row = warp * 4 + rr;
        const float* rp = (row < 16) ? &Ai[row][0] : &Aj[row - 16][0];
        float4 x = ((const float4*)rp)[lane];
        float ssum = x.x * x.x + x.y * x.y + x.z * x.z + x.w * x.w;
        #pragma unroll
        for (int o = 16; o > 0; o >>= 1) ssum += __shfl_xor_sync(0xffffffffu, ssum, o);
        if (lane == 0) {
            float rn = 1.0f / fmaxf(sqrtf(ssum), EPS_C);
            s_sq[row] = ssum * (rn * rn);
            s_ri[row] = rn;
        }
    }
    __syncthreads();

    const float4* ai = (const float4*)&Ai[ty][0];
    const float4* aj = (const float4*)&Aj[tx][0];
    float d0 = 0.f, d1 = 0.f, d2a = 0.f, d3 = 0.f;
    #pragma unroll 8
    for (int c = 0; c < 32; c++) {
        float4 a = ai[c];
        float4 bb = aj[c];
        d0  += a.x * bb.x;
        d1  += a.y * bb.y;
        d2a += a.z * bb.z;
        d3  += a.w * bb.w;
    }
    float dot = (d0 + d1) + (d2a + d3);
    float rij = s_ri[ty] * s_ri[16 + tx];
    float dd  = s_sq[ty] + s_sq[16 + tx] - 2.0f * (dot * rij);
    float d   = sqrtf(fmaxf(dd, 0.0f) + EPS_C);
    g_d[m][i][j] = d;
    if (bi != bj) g_d[m][j][i] = d;    // bitwise symmetric by construction
}

// ---------------- kernel 2: split-k triplet (f32x2) + combine + final -------
// grid: 640 blocks (i = bx>>1, kc = bx&1), 320 threads (one per j).
__global__ void __launch_bounds__(N) k_tripart(float* __restrict__ out) {
    int i  = blockIdx.x >> 1;
    int kc = blockIdx.x & 1;
    int t  = threadIdx.x;          // j

    __shared__ __align__(16) float sndk[N];   // -d_emb[i][k]
    __shared__ __align__(16) float sbk[N];    // 1 - pw[i][k]
    __shared__ __align__(16) float srbk[N];   // RHO * bk

    // prologue: each thread computes its own column's pw
    float d0j = g_d[0][i][t];
    float d1j = g_d[1][i][t];
    float dij = g_d[2][i][t];
    float pwij = 1.0f / (1.0f + expf(-RHO_C * (TAU_C - 0.5f * (d0j + d1j))));
    float bkj = 1.0f - pwij;
    sndk[t] = -dij;
    sbk[t]  = bkj;
    srbk[t] = RHO_C * bkj;
    __syncthreads();

    ull dij2 = pack2(dij, dij);
    ull M2   = pack2(MARGIN_C, MARGIN_C);
    ull npw2 = pack2(-pwij, -pwij);

    float maxA = 0.0f, maxB = 0.0f;
    float minA = 1e30f, minB = 1e30f;

    const ulonglong2* pnd = (const ulonglong2*)&sndk[kc * KCH];
    const ulonglong2* pbk = (const ulonglong2*)&sbk[kc * KCH];
    const ulonglong2* prb = (const ulonglong2*)&srbk[kc * KCH];

    // Per lane: t = dij + (-dk) == -(dk - dij) bitwise; m = M + t == M - diff.
    // k==j -> t==0 exactly -> m==0.2f exactly -> semihard (m <= MARGIN).
    #pragma unroll 4
    for (int q = 0; q < KCH / 4; q++) {
        ulonglong2 nd = pnd[q];        // 4 k's of -dk
        ulonglong2 bb = pbk[q];
        ulonglong2 rr = prb[q];
        {
            ull t2  = add2(dij2, nd.x);
            ull m2  = add2(M2, t2);
            ull vs2 = mul2(m2, bb.x);
            ull vh2 = fma2(rr.x, npw2, m2);
            float m0, m1, vs0, vs1, vh0, vh1;
            unpack2(m2, m0, m1); unpack2(vs2, vs0, vs1); unpack2(vh2, vh0, vh1);
            if (m0 <= MARGIN_C) maxA = fmaxf(maxA, vs0); else minA = fminf(minA, vh0);
            if (m1 <= MARGIN_C) maxB = fmaxf(maxB, vs1); else minB = fminf(minB, vh1);
        }
        {
            ull t2  = add2(dij2, nd.y);
            ull m2  = add2(M2, t2);
            ull vs2 = mul2(m2, bb.y);
            ull vh2 = fma2(rr.y, npw2, m2);
            float m0, m1, vs0, vs1, vh0, vh1;
            unpack2(m2, m0, m1); unpack2(vs2, vs0, vs1); unpack2(vh2, vh0, vh1);
            if (m0 <= MARGIN_C) maxA = fmaxf(maxA, vs0); else minA = fminf(minA, vh0);
            if (m1 <= MARGIN_C) maxB = fmaxf(maxB, vs1); else minB = fminf(minB, vh1);
        }
    }
    float maxs = fmaxf(maxA, maxB);    // fmax/fmin assoc+comm -> bit-exact combine
    float minn = fminf(minA, minB);

    __stcg(&g_mm[kc][i][t], make_float2(maxs, minn));
    __threadfence();

    // per-i ticket: second chunk block to finish combines row i
    __shared__ bool win_i;
    if (t == 0) win_i = (atomicAdd(&g_cnt_i[i], 1u) == 1u);
    __syncthreads();
    if (!win_i) return;

    float2 a = __ldcg(&g_mm[0][i][t]);
    float2 b = __ldcg(&g_mm[1][i][t]);
    float mx = fmaxf(a.x, b.x);
    float mn = fminf(a.y, b.y);
    float psh = pwij * mx;                          // pos_semihard
    float ph  = (mn < 0.0f) ? (mn + RHO_C) : 0.0f;
    float pos = psh + ((psh <= SEMIHARD_THRESH_C) ? ph : 0.0f);
    float contrib = pos * pwij;

    // deterministic dual block reduction: contrib (num) and pwij (den)
    float v = contrib, w = pwij;
    #pragma unroll
    for (int o = 16; o > 0; o >>= 1) {
        v += __shfl_down_sync(0xffffffffu, v, o);
        w += __shfl_down_sync(0xffffffffu, w, o);
    }
    __shared__ float swn[10], swd[10];
    int lane = t & 31, warp = t >> 5;
    if (lane == 0) { swn[warp] = v; swd[warp] = w; }
    __syncthreads();
    if (warp == 0 && lane == 0) {
        float sn = 0.0f, sd = 0.0f;
        #pragma unroll
        for (int q = 0; q < 10; q++) { sn += swn[q]; sd += swd[q]; }
        g_pnum[i] = sn;
        g_pden[i] = sd;
    }

    // ---- fused final: last winning block sums everything ----
    __threadfence();
    __shared__ bool is_last;
    if (t == 0) is_last = (atomicAdd(&g_counter, 1u) == (unsigned)(N - 1));
    __syncthreads();
    if (!is_last) return;

    float num = __ldcg(&g_pnum[t]);
    float den = __ldcg(&g_pden[t]);
    #pragma unroll
    for (int o = 16; o > 0; o >>= 1) {
        num += __shfl_down_sync(0xffffffffu, num, o);
        den += __shfl_down_sync(0xffffffffu, den, o);
    }
    __shared__ float sn2[10], sd2[10];
    if (lane == 0) { sn2[warp] = num; sd2[warp] = den; }
    __syncthreads();
    if (t == 0) {
        float fn = 0.0f, fd = 0.0f;
        #pragma unroll
        for (int q = 0; q < 10; q++) { fn += sn2[q]; fd += sd2[q]; }
        out[0] = (fd > 0.0f) ? (fn / fmaxf(fd, EPS_C)) : 0.0f;
    }
}

extern "C" void kernel_launch(void* const* d_in, const int* in_sizes, int n_in,
                              void* d_out, int out_size) {
    (void)n_in; (void)out_size;
    const float* src = (const float*)d_in[0];
    const float* emb = (const float*)d_in[1];
    if (n_in >= 2 && in_sizes[0] == N * D && in_sizes[1] == 2 * N * D) {
        const float* tmp = src; src = emb; emb = tmp;
    }
    float* out = (float*)d_out;

    k_dist<<<NMAT * NTRI, 256>>>(src, emb);
    k_tripart<<<2 * N, N>>>(out);
}